// round 1
// baseline (speedup 1.0000x reference)
#include <cuda_runtime.h>
#include <math.h>

#define NPTS 65536
#define NS   16
#define CH   128
#define EPSB 1e-5f

// scratch for Q, K, V (static device arrays: allocation-guard safe)
__device__ float g_q[(size_t)NPTS * CH];
__device__ float g_k[(size_t)NPTS * CH];
__device__ float g_v[(size_t)NPTS * CH];

// ---------------------------------------------------------------------------
// Kernel 1: QKV GEMM.  out[n_sel] = x @ W^T + b, M=65536, K=128.
// grid = (1024, 6): blockIdx.y in {0..5} -> (q|k|v) x (col half)
// 64x64 tile, 256 threads, 4x4 micro-tile, fp32.
// ---------------------------------------------------------------------------
__global__ void __launch_bounds__(256)
qkv_kernel(const float* __restrict__ x,
           const float* __restrict__ wq, const float* __restrict__ bq,
           const float* __restrict__ wk, const float* __restrict__ bk,
           const float* __restrict__ wv, const float* __restrict__ bv)
{
    __shared__ float As[64][65];
    __shared__ float Bs[64][65];

    const int m0  = blockIdx.x * 64;
    const int nch = blockIdx.y;

    const float* W;
    const float* bias;
    float* OUT;
    if (nch < 2)      { W = wq; bias = bq; OUT = g_q; }
    else if (nch < 4) { W = wk; bias = bk; OUT = g_k; }
    else              { W = wv; bias = bv; OUT = g_v; }
    const int ncol0 = (nch & 1) * 64;

    const int tid = threadIdx.x;
    const int tx  = tid & 15;   // n direction
    const int ty  = tid >> 4;   // m direction

    float acc[4][4];
#pragma unroll
    for (int i = 0; i < 4; ++i)
#pragma unroll
        for (int j = 0; j < 4; ++j) acc[i][j] = 0.f;

    for (int kc = 0; kc < 128; kc += 64) {
        // load 64x64 A and B tiles (coalesced along k)
#pragma unroll
        for (int i = 0; i < 16; ++i) {
            int lin = tid + i * 256;      // 0..4095
            int k = lin & 63;
            int m = lin >> 6;
            As[m][k] = x[(m0 + m) * 128 + kc + k];
            Bs[m][k] = W[(ncol0 + m) * 128 + kc + k];
        }
        __syncthreads();

#pragma unroll 16
        for (int k = 0; k < 64; ++k) {
            float a[4], b[4];
#pragma unroll
            for (int i = 0; i < 4; ++i) a[i] = As[ty * 4 + i][k];
#pragma unroll
            for (int j = 0; j < 4; ++j) b[j] = Bs[tx * 4 + j][k];
#pragma unroll
            for (int i = 0; i < 4; ++i)
#pragma unroll
                for (int j = 0; j < 4; ++j)
                    acc[i][j] = fmaf(a[i], b[j], acc[i][j]);
        }
        __syncthreads();
    }

#pragma unroll
    for (int i = 0; i < 4; ++i)
#pragma unroll
        for (int j = 0; j < 4; ++j) {
            int cc = ncol0 + tx * 4 + j;
            OUT[(m0 + ty * 4 + i) * 128 + cc] = acc[i][j] + bias[cc];
        }
}

// ---------------------------------------------------------------------------
// Reduce-scatter: 16 per-lane partials (indexed by o) summed across lanes,
// result for o = lane & 15 lands on that lane.
// with_x16=true also folds the two half-warps together (5th stage).
// ---------------------------------------------------------------------------
__device__ __forceinline__ float rs16(const float a[16],
                                      bool h8, bool h4, bool h2, bool h1,
                                      bool with_x16)
{
    float b[8];
#pragma unroll
    for (int k = 0; k < 8; ++k) {
        float s  = h8 ? a[k]     : a[k + 8];
        float kp = h8 ? a[k + 8] : a[k];
        b[k] = kp + __shfl_xor_sync(0xffffffffu, s, 8);
    }
    float c[4];
#pragma unroll
    for (int k = 0; k < 4; ++k) {
        float s  = h4 ? b[k]     : b[k + 4];
        float kp = h4 ? b[k + 4] : b[k];
        c[k] = kp + __shfl_xor_sync(0xffffffffu, s, 4);
    }
    float d[2];
#pragma unroll
    for (int k = 0; k < 2; ++k) {
        float s  = h2 ? c[k]     : c[k + 2];
        float kp = h2 ? c[k + 2] : c[k];
        d[k] = kp + __shfl_xor_sync(0xffffffffu, s, 2);
    }
    float s  = h1 ? d[0] : d[1];
    float kp = h1 ? d[1] : d[0];
    float e  = kp + __shfl_xor_sync(0xffffffffu, s, 1);
    if (with_x16) e += __shfl_xor_sync(0xffffffffu, e, 16);
    return e;
}

// ---------------------------------------------------------------------------
// Kernel 2: per-point neighborhood attention. One warp per point group.
// Lane owns channels {lane, lane+32, lane+64, lane+96}; softmax column
// u = c mod 16 = lane mod 16 is lane-local -> online softmax, single pass.
// ---------------------------------------------------------------------------
#define PPW 8   // points per warp

__global__ void __launch_bounds__(128, 3)
attn_kernel(const float* __restrict__ p,   const int* __restrict__ idx,
            const float* __restrict__ pw1, const float* __restrict__ pb1,
            const float* __restrict__ pbng, const float* __restrict__ pbnb,
            const float* __restrict__ pbnm, const float* __restrict__ pbnv,
            const float* __restrict__ pw2, const float* __restrict__ pb2,
            const float* __restrict__ bn1g, const float* __restrict__ bn1b,
            const float* __restrict__ bn1m, const float* __restrict__ bn1v,
            const float* __restrict__ ww1, const float* __restrict__ wb1,
            const float* __restrict__ bn2g, const float* __restrict__ bn2b,
            const float* __restrict__ bn2m, const float* __restrict__ bn2v,
            const float* __restrict__ ww2, const float* __restrict__ wb2,
            float* __restrict__ out)
{
    const int lane = threadIdx.x & 31;
    const int gw   = blockIdx.x * (blockDim.x >> 5) + (threadIdx.x >> 5);
    const int o    = lane & 15;

    // ---- per-lane constant parameters (loaded once, reused for PPW points)
    float w1c[16][4];
#pragma unroll
    for (int u = 0; u < 16; ++u)
#pragma unroll
        for (int r = 0; r < 4; ++r)
            w1c[u][r] = ww1[u * CH + lane + 32 * r];

    float w2col[16];
#pragma unroll
    for (int u = 0; u < 16; ++u) w2col[u] = ww2[u * 16 + o];

    const float b1o = wb1[o];
    const float s2  = bn2g[o] * rsqrtf(bn2v[o] + EPSB);
    const float b2f = bn2b[o] - bn2m[o] * s2;
    const float b2u = wb2[o];

    float s1[4], b1f[4], pw2v[4][3], pb2v[4];
#pragma unroll
    for (int r = 0; r < 4; ++r) {
        int c = lane + 32 * r;
        float s = bn1g[c] * rsqrtf(bn1v[c] + EPSB);
        s1[r]  = s;
        b1f[r] = bn1b[c] - bn1m[c] * s;
        pw2v[r][0] = pw2[c * 3 + 0];
        pw2v[r][1] = pw2[c * 3 + 1];
        pw2v[r][2] = pw2[c * 3 + 2];
        pb2v[r] = pb2[c];
    }
    float pw1v[9];
#pragma unroll
    for (int q = 0; q < 9; ++q) pw1v[q] = pw1[q];
    float pb1v[3], psc[3], psh[3];
#pragma unroll
    for (int a = 0; a < 3; ++a) {
        pb1v[a] = pb1[a];
        float s = pbng[a] * rsqrtf(pbnv[a] + EPSB);
        psc[a] = s;
        psh[a] = pbnb[a] - pbnm[a] * s;
    }

    const bool h8 = (lane & 8) != 0;
    const bool h4 = (lane & 4) != 0;
    const bool h2 = (lane & 2) != 0;
    const bool h1 = (lane & 1) != 0;

#pragma unroll 1
    for (int t = 0; t < PPW; ++t) {
        const int i = gw * PPW + t;

        float xq[4];
#pragma unroll
        for (int r = 0; r < 4; ++r) xq[r] = g_q[i * CH + lane + 32 * r];
        const float pi0 = p[i * 3 + 0];
        const float pi1 = p[i * 3 + 1];
        const float pi2 = p[i * 3 + 2];

        // all 16 neighbor indices via one coalesced load + shfl broadcast
        const int myj = idx[i * NS + (lane & 15)];

        float mrun = -INFINITY, Z = 0.f;
        float A[4] = {0.f, 0.f, 0.f, 0.f};

        // prefetch neighbor 0
        int jA = __shfl_sync(0xffffffffu, myj, 0);
        float gkA[4], gvA[4];
#pragma unroll
        for (int r = 0; r < 4; ++r) {
            gkA[r] = g_k[jA * CH + lane + 32 * r];
            gvA[r] = g_v[jA * CH + lane + 32 * r];
        }
        float pjA0 = p[jA * 3 + 0], pjA1 = p[jA * 3 + 1], pjA2 = p[jA * 3 + 2];

#pragma unroll 2
        for (int n = 0; n < NS; ++n) {
            // current neighbor registers
            float gk[4], gv[4];
#pragma unroll
            for (int r = 0; r < 4; ++r) { gk[r] = gkA[r]; gv[r] = gvA[r]; }
            float pr0 = pjA0 - pi0, pr1 = pjA1 - pi1, pr2 = pjA2 - pi2;

            // prefetch next neighbor (breaks the idx->gather latency chain)
            if (n < NS - 1) {
                int jn = __shfl_sync(0xffffffffu, myj, n + 1);
#pragma unroll
                for (int r = 0; r < 4; ++r) {
                    gkA[r] = g_k[jn * CH + lane + 32 * r];
                    gvA[r] = g_v[jn * CH + lane + 32 * r];
                }
                pjA0 = p[jn * 3 + 0]; pjA1 = p[jn * 3 + 1]; pjA2 = p[jn * 3 + 2];
            }

            // linear_p stage 1: 3x3 + BN + ReLU
            float tt[3];
#pragma unroll
            for (int a = 0; a < 3; ++a) {
                float v = fmaf(pr2, pw1v[a * 3 + 2],
                          fmaf(pr1, pw1v[a * 3 + 1],
                          fmaf(pr0, pw1v[a * 3 + 0], pb1v[a])));
                tt[a] = fmaxf(fmaf(v, psc[a], psh[a]), 0.f);
            }
            // linear_p stage 2: 3 -> 128 (4 chans/lane)
            float pe[4], wp[4];
#pragma unroll
            for (int r = 0; r < 4; ++r) {
                pe[r] = fmaf(tt[2], pw2v[r][2],
                        fmaf(tt[1], pw2v[r][1],
                        fmaf(tt[0], pw2v[r][0], pb2v[r])));
                wp[r] = fmaxf(fmaf(gk[r] - xq[r] + pe[r], s1[r], b1f[r]), 0.f);
            }

            // w1 = wpre @ w_w1^T : per-lane partials then reduce-scatter
            float a16[16];
#pragma unroll
            for (int u = 0; u < 16; ++u)
                a16[u] = fmaf(wp[3], w1c[u][3],
                         fmaf(wp[2], w1c[u][2],
                         fmaf(wp[1], w1c[u][1], wp[0] * w1c[u][0])));
            float w1v = rs16(a16, h8, h4, h2, h1, true) + b1o;

            // BN2 + ReLU
            float tv = fmaxf(fmaf(w1v, s2, b2f), 0.f);

            // w2 = t @ w_w2^T : partials + half-warp reduce-scatter
            float q16[16];
#pragma unroll
            for (int u = 0; u < 16; ++u) q16[u] = tv * w2col[u];
            float w2v = rs16(q16, h8, h4, h2, h1, false) + b2u;

            // online softmax over neighbors (lane-local column u = lane&15)
            float nm   = fmaxf(mrun, w2v);
            float corr = __expf(mrun - nm);
            float e    = __expf(w2v - nm);
            Z = fmaf(Z, corr, e);
#pragma unroll
            for (int r = 0; r < 4; ++r)
                A[r] = fmaf(A[r], corr, (gv[r] + pe[r]) * e);
            mrun = nm;
        }

        const float inv = __frcp_rn(Z);
#pragma unroll
        for (int r = 0; r < 4; ++r)
            out[i * CH + lane + 32 * r] = A[r] * inv;
    }
}

// ---------------------------------------------------------------------------
extern "C" void kernel_launch(void* const* d_in, const int* in_sizes, int n_in,
                              void* d_out, int out_size)
{
    const float* p    = (const float*)d_in[0];
    const float* x    = (const float*)d_in[1];
    const int*   idx  = (const int*)  d_in[2];
    const float* wq   = (const float*)d_in[3];
    const float* bq   = (const float*)d_in[4];
    const float* wk   = (const float*)d_in[5];
    const float* bk   = (const float*)d_in[6];
    const float* wv   = (const float*)d_in[7];
    const float* bv   = (const float*)d_in[8];
    const float* pw1  = (const float*)d_in[9];
    const float* pb1  = (const float*)d_in[10];
    const float* pbng = (const float*)d_in[11];
    const float* pbnb = (const float*)d_in[12];
    const float* pbnm = (const float*)d_in[13];
    const float* pbnv = (const float*)d_in[14];
    const float* pw2  = (const float*)d_in[15];
    const float* pb2  = (const float*)d_in[16];
    const float* bn1g = (const float*)d_in[17];
    const float* bn1b = (const float*)d_in[18];
    const float* bn1m = (const float*)d_in[19];
    const float* bn1v = (const float*)d_in[20];
    const float* ww1  = (const float*)d_in[21];
    const float* wb1  = (const float*)d_in[22];
    const float* bn2g = (const float*)d_in[23];
    const float* bn2b = (const float*)d_in[24];
    const float* bn2m = (const float*)d_in[25];
    const float* bn2v = (const float*)d_in[26];
    const float* ww2  = (const float*)d_in[27];
    const float* wb2  = (const float*)d_in[28];
    float* out = (float*)d_out;

    qkv_kernel<<<dim3(NPTS / 64, 6), 256>>>(x, wq, bq, wk, bk, wv, bv);

    attn_kernel<<<NPTS / (PPW * 4), 128>>>(
        p, idx,
        pw1, pb1, pbng, pbnb, pbnm, pbnv, pw2, pb2,
        bn1g, bn1b, bn1m, bn1v, ww1, wb1,
        bn2g, bn2b, bn2m, bn2v, ww2, wb2,
        out);
}

// round 2
// speedup vs baseline: 1.3376x; 1.3376x over previous
#include <cuda_runtime.h>
#include <math.h>

#define NPTS 65536
#define NS   16
#define CH   128
#define EPSB 1e-5f

typedef unsigned long long ull;

__device__ __forceinline__ ull pack2(float lo, float hi) {
    ull r; asm("mov.b64 %0,{%1,%2};" : "=l"(r) : "f"(lo), "f"(hi)); return r;
}
__device__ __forceinline__ void unpack2(ull v, float& lo, float& hi) {
    asm("mov.b64 {%0,%1},%2;" : "=f"(lo), "=f"(hi) : "l"(v));
}
__device__ __forceinline__ ull ffma2(ull a, ull b, ull c) {
    ull d; asm("fma.rn.f32x2 %0,%1,%2,%3;" : "=l"(d) : "l"(a), "l"(b), "l"(c)); return d;
}
__device__ __forceinline__ ull fmul2(ull a, ull b) {
    ull d; asm("mul.rn.f32x2 %0,%1,%2;" : "=l"(d) : "l"(a), "l"(b)); return d;
}

// scratch for Q, K, V (static device arrays: allocation-guard safe)
__device__ float g_q[(size_t)NPTS * CH];
__device__ float g_k[(size_t)NPTS * CH];
__device__ float g_v[(size_t)NPTS * CH];

// ---------------------------------------------------------------------------
// Kernel 1: QKV GEMM. 128x128 tile, 256 threads, 8x8 micro-tile, f32x2 FFMA2,
// K pipelined in 4 chunks of 32 with register prefetch.
// grid = (512, 3): blockIdx.y selects q/k/v.
// ---------------------------------------------------------------------------
#define PADM 132

__global__ void __launch_bounds__(256)
qkv_kernel(const float* __restrict__ x,
           const float* __restrict__ wq, const float* __restrict__ bq,
           const float* __restrict__ wk, const float* __restrict__ bk,
           const float* __restrict__ wv, const float* __restrict__ bv)
{
    __shared__ float Xs[32][PADM];   // [k][m]
    __shared__ float Ws[32][PADM];   // [k][n]

    const int m0 = blockIdx.x * 128;
    const float* W;
    const float* bias;
    float* OUT;
    if (blockIdx.y == 0)      { W = wq; bias = bq; OUT = g_q; }
    else if (blockIdx.y == 1) { W = wk; bias = bk; OUT = g_k; }
    else                      { W = wv; bias = bv; OUT = g_v; }

    const int tid = threadIdx.x;
    const int tx  = tid & 15;    // n dir
    const int ty  = tid >> 4;    // m dir

    const int lrow = tid >> 3;          // 0..31
    const int kq   = (tid & 7) * 4;     // 0,4,..28

    ull acc2[8][4];
#pragma unroll
    for (int i = 0; i < 8; ++i)
#pragma unroll
        for (int j = 0; j < 4; ++j) acc2[i][j] = 0ull;

    // prefetch chunk 0
    float4 xpre[4], wpre[4];
#pragma unroll
    for (int l = 0; l < 4; ++l) {
        xpre[l] = *(const float4*)&x[(size_t)(m0 + lrow + 32 * l) * 128 + kq];
        wpre[l] = *(const float4*)&W[(size_t)(lrow + 32 * l) * 128 + kq];
    }

#pragma unroll
    for (int c = 0; c < 4; ++c) {
        // stage prefetched chunk into smem (transposed)
#pragma unroll
        for (int l = 0; l < 4; ++l) {
            int row = lrow + 32 * l;
            Xs[kq + 0][row] = xpre[l].x; Xs[kq + 1][row] = xpre[l].y;
            Xs[kq + 2][row] = xpre[l].z; Xs[kq + 3][row] = xpre[l].w;
            Ws[kq + 0][row] = wpre[l].x; Ws[kq + 1][row] = wpre[l].y;
            Ws[kq + 2][row] = wpre[l].z; Ws[kq + 3][row] = wpre[l].w;
        }
        __syncthreads();

        if (c < 3) {
            int kc = (c + 1) * 32;
#pragma unroll
            for (int l = 0; l < 4; ++l) {
                xpre[l] = *(const float4*)&x[(size_t)(m0 + lrow + 32 * l) * 128 + kc + kq];
                wpre[l] = *(const float4*)&W[(size_t)(lrow + 32 * l) * 128 + kc + kq];
            }
        }

#pragma unroll 8
        for (int k = 0; k < 32; ++k) {
            float4 a0 = *(const float4*)&Xs[k][ty * 8];
            float4 a1 = *(const float4*)&Xs[k][ty * 8 + 4];
            float4 b0 = *(const float4*)&Ws[k][tx * 8];
            float4 b1 = *(const float4*)&Ws[k][tx * 8 + 4];
            ull bb[4];
            bb[0] = pack2(b0.x, b0.y); bb[1] = pack2(b0.z, b0.w);
            bb[2] = pack2(b1.x, b1.y); bb[3] = pack2(b1.z, b1.w);
            float av[8] = {a0.x, a0.y, a0.z, a0.w, a1.x, a1.y, a1.z, a1.w};
#pragma unroll
            for (int i = 0; i < 8; ++i) {
                ull ai = pack2(av[i], av[i]);
#pragma unroll
                for (int j = 0; j < 4; ++j)
                    acc2[i][j] = ffma2(ai, bb[j], acc2[i][j]);
            }
        }
        __syncthreads();
    }

    // bias + store
    float bs[8];
    {
        float4 t0 = *(const float4*)&bias[tx * 8];
        float4 t1 = *(const float4*)&bias[tx * 8 + 4];
        bs[0] = t0.x; bs[1] = t0.y; bs[2] = t0.z; bs[3] = t0.w;
        bs[4] = t1.x; bs[5] = t1.y; bs[6] = t1.z; bs[7] = t1.w;
    }
#pragma unroll
    for (int i = 0; i < 8; ++i) {
        float v[8];
#pragma unroll
        for (int j = 0; j < 4; ++j) unpack2(acc2[i][j], v[2 * j], v[2 * j + 1]);
        float4 o0 = make_float4(v[0] + bs[0], v[1] + bs[1], v[2] + bs[2], v[3] + bs[3]);
        float4 o1 = make_float4(v[4] + bs[4], v[5] + bs[5], v[6] + bs[6], v[7] + bs[7]);
        size_t base = (size_t)(m0 + ty * 8 + i) * 128 + tx * 8;
        *(float4*)&OUT[base]     = o0;
        *(float4*)&OUT[base + 4] = o1;
    }
}

// ---------------------------------------------------------------------------
// Kernel 2: per-point neighborhood attention. Lane owns channels lane+32r.
// Softmax column o = lane&15 is lane-local -> online softmax, one pass.
// GEMV1 (128->16): f32x2 partials + XOR-permuted reduce-scatter (no selects).
// GEMV2 (16->16): broadcast shfl form.
// ---------------------------------------------------------------------------
#define PPW 8   // points per warp

__global__ void __launch_bounds__(128, 3)
attn_kernel(const float* __restrict__ p,   const int* __restrict__ idx,
            const float* __restrict__ pw1, const float* __restrict__ pb1,
            const float* __restrict__ pbng, const float* __restrict__ pbnb,
            const float* __restrict__ pbnm, const float* __restrict__ pbnv,
            const float* __restrict__ pw2, const float* __restrict__ pb2,
            const float* __restrict__ bn1g, const float* __restrict__ bn1b,
            const float* __restrict__ bn1m, const float* __restrict__ bn1v,
            const float* __restrict__ ww1, const float* __restrict__ wb1,
            const float* __restrict__ bn2g, const float* __restrict__ bn2b,
            const float* __restrict__ bn2m, const float* __restrict__ bn2v,
            const float* __restrict__ ww2, const float* __restrict__ wb2,
            float* __restrict__ out)
{
    const int lane = threadIdx.x & 31;
    const int gw   = blockIdx.x * (blockDim.x >> 5) + (threadIdx.x >> 5);
    const int o    = lane & 15;

    // --- per-lane constants ---
    // w1c2[j][r] = pack( ww1[(o^(2j))*CH + c_r], ww1[(o^(2j+1))*CH + c_r] )
    ull w1c2[8][4];
#pragma unroll
    for (int j = 0; j < 8; ++j)
#pragma unroll
        for (int r = 0; r < 4; ++r) {
            int c = lane + 32 * r;
            w1c2[j][r] = pack2(ww1[(o ^ (2 * j)) * CH + c],
                               ww1[(o ^ (2 * j + 1)) * CH + c]);
        }

    float w2r[16];
#pragma unroll
    for (int u = 0; u < 16; ++u) w2r[u] = ww2[o * 16 + u];

    const float s2    = bn2g[o] * rsqrtf(bn2v[o] + EPSB);
    const float b2fld = bn2b[o] - bn2m[o] * s2 + wb1[o] * s2;  // folds w1 bias
    const float b2u   = wb2[o];

    float s1[4], b1f[4], pw2v[4][3], pb2v[4];
#pragma unroll
    for (int r = 0; r < 4; ++r) {
        int c = lane + 32 * r;
        float s = bn1g[c] * rsqrtf(bn1v[c] + EPSB);
        s1[r]  = s;
        b1f[r] = bn1b[c] - bn1m[c] * s;
        pw2v[r][0] = pw2[c * 3 + 0];
        pw2v[r][1] = pw2[c * 3 + 1];
        pw2v[r][2] = pw2[c * 3 + 2];
        pb2v[r] = pb2[c];
    }
    float pw1v[9];
#pragma unroll
    for (int q = 0; q < 9; ++q) pw1v[q] = pw1[q];
    float pb1v[3], psc[3], psh[3];
#pragma unroll
    for (int a = 0; a < 3; ++a) {
        pb1v[a] = pb1[a];
        float s = pbng[a] * rsqrtf(pbnv[a] + EPSB);
        psc[a] = s;
        psh[a] = pbnb[a] - pbnm[a] * s;
    }

#pragma unroll 1
    for (int t = 0; t < PPW; ++t) {
        const int i = gw * PPW + t;

        float xq[4];
#pragma unroll
        for (int r = 0; r < 4; ++r) xq[r] = g_q[(size_t)i * CH + lane + 32 * r];
        const float pi0 = p[i * 3 + 0];
        const float pi1 = p[i * 3 + 1];
        const float pi2 = p[i * 3 + 2];

        const int myj = idx[i * NS + o];

        float mrun = -INFINITY, Z = 0.f;
        float A[4] = {0.f, 0.f, 0.f, 0.f};

        // prefetch neighbor 0
        int jA = __shfl_sync(0xffffffffu, myj, 0);
        float gkA[4], gvA[4];
#pragma unroll
        for (int r = 0; r < 4; ++r) {
            gkA[r] = g_k[(size_t)jA * CH + lane + 32 * r];
            gvA[r] = g_v[(size_t)jA * CH + lane + 32 * r];
        }
        float pjA0 = p[jA * 3 + 0], pjA1 = p[jA * 3 + 1], pjA2 = p[jA * 3 + 2];

#pragma unroll 2
        for (int n = 0; n < NS; ++n) {
            float gk[4], gv[4];
#pragma unroll
            for (int r = 0; r < 4; ++r) { gk[r] = gkA[r]; gv[r] = gvA[r]; }
            float pr0 = pjA0 - pi0, pr1 = pjA1 - pi1, pr2 = pjA2 - pi2;

            if (n < NS - 1) {
                int jn = __shfl_sync(0xffffffffu, myj, n + 1);
#pragma unroll
                for (int r = 0; r < 4; ++r) {
                    gkA[r] = g_k[(size_t)jn * CH + lane + 32 * r];
                    gvA[r] = g_v[(size_t)jn * CH + lane + 32 * r];
                }
                pjA0 = p[jn * 3 + 0]; pjA1 = p[jn * 3 + 1]; pjA2 = p[jn * 3 + 2];
            }

            // linear_p stage 1: 3x3 + BN + ReLU
            float tt[3];
#pragma unroll
            for (int a = 0; a < 3; ++a) {
                float v = fmaf(pr2, pw1v[a * 3 + 2],
                          fmaf(pr1, pw1v[a * 3 + 1],
                          fmaf(pr0, pw1v[a * 3 + 0], pb1v[a])));
                tt[a] = fmaxf(fmaf(v, psc[a], psh[a]), 0.f);
            }
            // linear_p stage 2 + w-pre (BN1+ReLU)
            float pe[4], wp[4];
#pragma unroll
            for (int r = 0; r < 4; ++r) {
                pe[r] = fmaf(tt[2], pw2v[r][2],
                        fmaf(tt[1], pw2v[r][1],
                        fmaf(tt[0], pw2v[r][0], pb2v[r])));
                wp[r] = fmaxf(fmaf(gk[r] - xq[r] + pe[r], s1[r], b1f[r]), 0.f);
            }

            // GEMV1 partials: a[k] = partial for output (o ^ k), packed f32x2
            ull wp2[4];
#pragma unroll
            for (int r = 0; r < 4; ++r) wp2[r] = pack2(wp[r], wp[r]);
            ull acc2[8];
#pragma unroll
            for (int j = 0; j < 8; ++j) {
                acc2[j] = fmul2(wp2[0], w1c2[j][0]);
                acc2[j] = ffma2(wp2[1], w1c2[j][1], acc2[j]);
                acc2[j] = ffma2(wp2[2], w1c2[j][2], acc2[j]);
                acc2[j] = ffma2(wp2[3], w1c2[j][3], acc2[j]);
            }
            float a[16];
#pragma unroll
            for (int j = 0; j < 8; ++j) unpack2(acc2[j], a[2 * j], a[2 * j + 1]);

            // XOR reduce-scatter: 15 shfl + 15 add, no selects
#pragma unroll
            for (int k = 0; k < 8; ++k) a[k] += __shfl_xor_sync(0xffffffffu, a[k + 8], 8);
#pragma unroll
            for (int k = 0; k < 4; ++k) a[k] += __shfl_xor_sync(0xffffffffu, a[k + 4], 4);
#pragma unroll
            for (int k = 0; k < 2; ++k) a[k] += __shfl_xor_sync(0xffffffffu, a[k + 2], 2);
            a[0] += __shfl_xor_sync(0xffffffffu, a[1], 1);
            float w1s = a[0] + __shfl_xor_sync(0xffffffffu, a[0], 16);

            // BN2 + ReLU (w1 bias folded into b2fld)
            float tv = fmaxf(fmaf(w1s, s2, b2fld), 0.f);

            // GEMV2 broadcast form: 16 shfl + 16 fma
            float w2v = b2u;
#pragma unroll
            for (int u = 0; u < 16; ++u)
                w2v = fmaf(__shfl_sync(0xffffffffu, tv, u), w2r[u], w2v);

            // online softmax (column o is lane-local)
            float nm   = fmaxf(mrun, w2v);
            float corr = __expf(mrun - nm);
            float e    = __expf(w2v - nm);
            Z = fmaf(Z, corr, e);
#pragma unroll
            for (int r = 0; r < 4; ++r)
                A[r] = fmaf(A[r], corr, (gv[r] + pe[r]) * e);
            mrun = nm;
        }

        const float inv = __frcp_rn(Z);
#pragma unroll
        for (int r = 0; r < 4; ++r)
            out[(size_t)i * CH + lane + 32 * r] = A[r] * inv;
    }
}

// ---------------------------------------------------------------------------
extern "C" void kernel_launch(void* const* d_in, const int* in_sizes, int n_in,
                              void* d_out, int out_size)
{
    const float* p    = (const float*)d_in[0];
    const float* x    = (const float*)d_in[1];
    const int*   idx  = (const int*)  d_in[2];
    const float* wq   = (const float*)d_in[3];
    const float* bq   = (const float*)d_in[4];
    const float* wk   = (const float*)d_in[5];
    const float* bk   = (const float*)d_in[6];
    const float* wv   = (const float*)d_in[7];
    const float* bv   = (const float*)d_in[8];
    const float* pw1  = (const float*)d_in[9];
    const float* pb1  = (const float*)d_in[10];
    const float* pbng = (const float*)d_in[11];
    const float* pbnb = (const float*)d_in[12];
    const float* pbnm = (const float*)d_in[13];
    const float* pbnv = (const float*)d_in[14];
    const float* pw2  = (const float*)d_in[15];
    const float* pb2  = (const float*)d_in[16];
    const float* bn1g = (const float*)d_in[17];
    const float* bn1b = (const float*)d_in[18];
    const float* bn1m = (const float*)d_in[19];
    const float* bn1v = (const float*)d_in[20];
    const float* ww1  = (const float*)d_in[21];
    const float* wb1  = (const float*)d_in[22];
    const float* bn2g = (const float*)d_in[23];
    const float* bn2b = (const float*)d_in[24];
    const float* bn2m = (const float*)d_in[25];
    const float* bn2v = (const float*)d_in[26];
    const float* ww2  = (const float*)d_in[27];
    const float* wb2  = (const float*)d_in[28];
    float* out = (float*)d_out;

    qkv_kernel<<<dim3(NPTS / 128, 3), 256>>>(x, wq, bq, wk, bk, wv, bv);

    attn_kernel<<<NPTS / (PPW * 4), 128>>>(
        p, idx,
        pw1, pb1, pbng, pbnb, pbnm, pbnv, pw2, pb2,
        bn1g, bn1b, bn1m, bn1v, ww1, wb1,
        bn2g, bn2b, bn2m, bn2v, ww2, wb2,
        out);
}